// round 6
// baseline (speedup 1.0000x reference)
#include <cuda_runtime.h>
#include <cstdint>
#include <cstddef>

#define M_TOTAL 4096
#define N_TOTAL 16384
#define K_TOTAL 4096
#define BM 128
#define BN 128
#define BK 64
#define KT (K_TOTAL / BK)               // 64
#define STAGES 4
#define AH_BYTES (BM * BK)              // 8 KB  (int8, 64B rows)
#define B_BYTES  (BN * BK)              // 8 KB
#define STAGE_BYTES (2 * AH_BYTES + B_BYTES)   // 24 KB (Ahi, Alo, B)
#define SMEM_TOTAL (STAGES * STAGE_BYTES)      // 96 KB

#define QMAX 16256   // 127*128

// int8 scratch
__device__ __align__(1024) signed char g_Xhi[(size_t)M_TOTAL * K_TOTAL];  // 16 MB
__device__ __align__(1024) signed char g_Xlo[(size_t)M_TOTAL * K_TOTAL];  // 16 MB
__device__ __align__(1024) signed char g_W8[(size_t)N_TOTAL * K_TOTAL];   // 64 MB
__device__ float g_rowsum[M_TOTAL];
__device__ unsigned g_maxbits;
__device__ float g_s, g_sinv, g_dz;

// ---------------- helpers ----------------
__device__ __forceinline__ uint32_t smem_u32(const void* p) {
    uint32_t a;
    asm("{ .reg .u64 t; cvta.to.shared.u64 t, %1; cvt.u32.u64 %0, t; }" : "=r"(a) : "l"(p));
    return a;
}

__device__ __forceinline__ void ldsm_x4(uint32_t& r0, uint32_t& r1, uint32_t& r2, uint32_t& r3,
                                        uint32_t addr) {
    asm volatile("ldmatrix.sync.aligned.m8n8.x4.shared.b16 {%0,%1,%2,%3}, [%4];"
                 : "=r"(r0), "=r"(r1), "=r"(r2), "=r"(r3) : "r"(addr));
}

// d = A*B (fresh, C=0)
__device__ __forceinline__ void imma_zero(int* d, const uint32_t* a, uint32_t b0, uint32_t b1) {
    asm volatile(
        "mma.sync.aligned.m16n8k32.row.col.s32.s8.s8.s32 "
        "{%0,%1,%2,%3}, {%4,%5,%6,%7}, {%8,%9}, {%10,%11,%12,%13};"
        : "=r"(d[0]), "=r"(d[1]), "=r"(d[2]), "=r"(d[3])
        : "r"(a[0]), "r"(a[1]), "r"(a[2]), "r"(a[3]), "r"(b0), "r"(b1),
          "r"(0), "r"(0), "r"(0), "r"(0));
}

// c += A*B
__device__ __forceinline__ void imma_acc(int* c, const uint32_t* a, uint32_t b0, uint32_t b1) {
    asm volatile(
        "mma.sync.aligned.m16n8k32.row.col.s32.s8.s8.s32 "
        "{%0,%1,%2,%3}, {%4,%5,%6,%7}, {%8,%9}, {%0,%1,%2,%3};"
        : "+r"(c[0]), "+r"(c[1]), "+r"(c[2]), "+r"(c[3])
        : "r"(a[0]), "r"(a[1]), "r"(a[2]), "r"(a[3]), "r"(b0), "r"(b1));
}

// ---------------- prep kernels ----------------
__global__ void k_reset() { g_maxbits = 0u; }

__global__ void __launch_bounds__(256) k_max(const float4* __restrict__ x) {
    float m = 0.0f;
    int stride = gridDim.x * blockDim.x;
    for (int i = blockIdx.x * blockDim.x + threadIdx.x;
         i < M_TOTAL * K_TOTAL / 4; i += stride) {
        float4 v = x[i];
        m = fmaxf(m, fmaxf(fmaxf(fabsf(v.x), fabsf(v.y)), fmaxf(fabsf(v.z), fabsf(v.w))));
    }
#pragma unroll
    for (int o = 16; o > 0; o >>= 1)
        m = fmaxf(m, __shfl_xor_sync(0xFFFFFFFFu, m, o));
    if ((threadIdx.x & 31) == 0)
        atomicMax(&g_maxbits, __float_as_uint(m));   // m>=0: uint order == float order
}

__global__ void k_scale(const float* __restrict__ zp) {
    float mx = __uint_as_float(g_maxbits);
    g_s    = mx / (float)QMAX;
    g_sinv = (mx > 0.0f) ? ((float)QMAX / mx) : 0.0f;
    float z = *zp;
    g_dz = rintf(z) - z;                              // W = Wint + dz
}

__global__ void __launch_bounds__(256) k_rowsum(const float* __restrict__ x) {
    __shared__ float red[256];
    const int row = blockIdx.x;
    const float* p = x + (size_t)row * K_TOTAL;
    float s = 0.0f;
    for (int i = threadIdx.x; i < K_TOTAL; i += 256) s += p[i];
    red[threadIdx.x] = s;
    __syncthreads();
    for (int o = 128; o > 0; o >>= 1) {
        if (threadIdx.x < o) red[threadIdx.x] += red[threadIdx.x + o];
        __syncthreads();
    }
    if (threadIdx.x == 0) g_rowsum[row] = red[0];
}

__global__ void __launch_bounds__(256) cvt_x_kernel(const float4* __restrict__ x) {
    const float si = g_sinv;
    int i = blockIdx.x * blockDim.x + threadIdx.x;    // exact grid
    float4 v = x[i];
    int v0 = min(max(__float2int_rn(v.x * si), -QMAX), QMAX);
    int v1 = min(max(__float2int_rn(v.y * si), -QMAX), QMAX);
    int v2 = min(max(__float2int_rn(v.z * si), -QMAX), QMAX);
    int v3 = min(max(__float2int_rn(v.w * si), -QMAX), QMAX);
    int h0 = (v0 + 64) >> 7, h1 = (v1 + 64) >> 7, h2 = (v2 + 64) >> 7, h3 = (v3 + 64) >> 7;
    char4 hi = make_char4((signed char)h0, (signed char)h1, (signed char)h2, (signed char)h3);
    char4 lo = make_char4((signed char)(v0 - (h0 << 7)), (signed char)(v1 - (h1 << 7)),
                          (signed char)(v2 - (h2 << 7)), (signed char)(v3 - (h3 << 7)));
    *reinterpret_cast<char4*>(&g_Xhi[(size_t)i * 4]) = hi;
    *reinterpret_cast<char4*>(&g_Xlo[(size_t)i * 4]) = lo;
}

__global__ void __launch_bounds__(256) cvt_w_kernel(const int4* __restrict__ w,
                                                    const float* __restrict__ zp) {
    const int zr = (int)rintf(__ldg(zp));
    int i = blockIdx.x * blockDim.x + threadIdx.x;
    int4 q = w[i];
    char4 o = make_char4((signed char)min(max(q.x - zr, -128), 127),
                         (signed char)min(max(q.y - zr, -128), 127),
                         (signed char)min(max(q.z - zr, -128), 127),
                         (signed char)min(max(q.w - zr, -128), 127));
    *reinterpret_cast<char4*>(&g_W8[(size_t)i * 4]) = o;
}

// ---------------- int8 dual GEMM ----------------
// acc = 128*(Xhi . W) + (Xlo . W), exact int32; out = g_s*scale*acc + scale*dz*rowsum + bias
__global__ void __launch_bounds__(256, 2)
gemm_imma_kernel(const float* __restrict__ scale_p,
                 const float* __restrict__ bias,
                 float* __restrict__ out)
{
    extern __shared__ __align__(1024) char smem[];
    const uint32_t smem_base = smem_u32(smem);
    const int tid  = threadIdx.x;
    const int wid  = tid >> 5;
    const int lane = tid & 31;
    const int mw = wid & 3;          // 4 warps along M (32 rows each)
    const int nw = wid >> 2;         // 2 warps along N (64 cols each)
    const int mtile = blockIdx.x;
    const int ntile = blockIdx.y;

    const char* gAh = (const char*)g_Xhi + (size_t)mtile * BM * K_TOTAL;
    const char* gAl = (const char*)g_Xlo + (size_t)mtile * BM * K_TOTAL;
    const char* gB  = (const char*)g_W8  + (size_t)ntile * BN * K_TOTAL;

    // 64B rows; SW64 swizzle: off ^ ((off>>3)&0x30), xor term = (row&6)<<3
    auto load_stage = [&](int kt, int stage) {
        const uint32_t sAh = smem_base + stage * STAGE_BYTES;
        const uint32_t sAl = sAh + AH_BYTES;
        const uint32_t sB  = sAl + AH_BYTES;
        const char* pAh = gAh + (size_t)kt * BK;
        const char* pAl = gAl + (size_t)kt * BK;
        const char* pB  = gB  + (size_t)kt * BK;
#pragma unroll
        for (int i = 0; i < 2; i++) {
            int ci  = i * 256 + tid;
            int row = ci >> 2;                 // 0..127
            int c   = ci & 3;                  // 16B chunk in 64B row
            uint32_t off = (uint32_t)(row * 64 + c * 16);
            uint32_t sw  = off ^ ((off >> 3) & 0x30);
            asm volatile("cp.async.cg.shared.global [%0], [%1], 16;"
                         :: "r"(sAh + sw), "l"(pAh + (size_t)row * K_TOTAL + c * 16));
            asm volatile("cp.async.cg.shared.global [%0], [%1], 16;"
                         :: "r"(sAl + sw), "l"(pAl + (size_t)row * K_TOTAL + c * 16));
            asm volatile("cp.async.cg.shared.global [%0], [%1], 16;"
                         :: "r"(sB  + sw), "l"(pB  + (size_t)row * K_TOTAL + c * 16));
        }
        asm volatile("cp.async.commit_group;" ::: "memory");
    };

    // ldmatrix address prep: addr = base + ((lin + q*32) ^ xor), xor row-only
    uint32_t aLin[2], aXor[2];
#pragma unroll
    for (int t = 0; t < 2; t++) {
        int row = mw * 32 + t * 16 + (lane & 15);
        aLin[t] = (uint32_t)(row * 64 + (lane >> 4) * 16);
        aXor[t] = (uint32_t)((row & 6) << 3);
    }
    uint32_t bLin[4], bXor[4];
#pragma unroll
    for (int u = 0; u < 4; u++) {
        int g = lane >> 3, r = lane & 7;
        int row = nw * 64 + u * 16 + ((g >> 1) << 3) + r;
        bLin[u] = (uint32_t)(row * 64 + (g & 1) * 16);
        bXor[u] = (uint32_t)((row & 6) << 3);
    }

    int acc[2][8][4];
#pragma unroll
    for (int t = 0; t < 2; t++)
#pragma unroll
        for (int n = 0; n < 8; n++)
#pragma unroll
            for (int j = 0; j < 4; j++) acc[t][n][j] = 0;

    load_stage(0, 0);
    load_stage(1, 1);
    load_stage(2, 2);

    for (int kt = 0; kt < KT; kt++) {
        asm volatile("cp.async.wait_group %0;" :: "n"(STAGES - 2) : "memory");
        __syncthreads();

        const int pf = kt + STAGES - 1;
        if (pf < KT) {
            load_stage(pf, pf % STAGES);
        } else {
            asm volatile("cp.async.commit_group;" ::: "memory");
        }

        const uint32_t sAh = smem_base + (kt % STAGES) * STAGE_BYTES;
        const uint32_t sAl = sAh + AH_BYTES;
        const uint32_t sB  = sAl + AH_BYTES;

#pragma unroll
        for (int q = 0; q < 2; q++) {          // two k32 chunks
            uint32_t ah[2][4], al[2][4];
#pragma unroll
            for (int t = 0; t < 2; t++) {
                uint32_t rel = (aLin[t] + q * 32) ^ aXor[t];
                ldsm_x4(ah[t][0], ah[t][1], ah[t][2], ah[t][3], sAh + rel);
                ldsm_x4(al[t][0], al[t][1], al[t][2], al[t][3], sAl + rel);
            }
#pragma unroll
            for (int u = 0; u < 4; u++) {
                uint32_t b[4];
                ldsm_x4(b[0], b[1], b[2], b[3], sB + ((bLin[u] + q * 32) ^ bXor[u]));
#pragma unroll
                for (int nn = 0; nn < 2; nn++) {
                    uint32_t b0 = b[nn * 2], b1 = b[nn * 2 + 1];
#pragma unroll
                    for (int t = 0; t < 2; t++) {
                        const int n = 2 * u + nn;
                        int d[4];
                        imma_zero(d, ah[t], b0, b1);
#pragma unroll
                        for (int j = 0; j < 4; j++)
                            acc[t][n][j] += d[j] << 7;          // fold hi*128
                        imma_acc(acc[t][n], al[t], b0, b1);     // += lo
                    }
                }
            }
        }
    }

    // epilogue
    const float scl = __ldg(scale_p);
    const float sscl = g_s * scl;
    const float dzs = g_dz * scl;
    const int rbase = mtile * BM + mw * 32 + (lane >> 2);
    const int cbase = ntile * BN + nw * 64 + (lane & 3) * 2;
#pragma unroll
    for (int t = 0; t < 2; t++) {
        const int r0 = rbase + t * 16;
        const float corr0 = dzs * g_rowsum[r0];
        const float corr1 = dzs * g_rowsum[r0 + 8];
#pragma unroll
        for (int n = 0; n < 8; n++) {
            const int col = cbase + n * 8;
            const float2 bb = *reinterpret_cast<const float2*>(bias + col);
            float2 v0, v1;
            v0.x = (float)acc[t][n][0] * sscl + corr0 + bb.x;
            v0.y = (float)acc[t][n][1] * sscl + corr0 + bb.y;
            v1.x = (float)acc[t][n][2] * sscl + corr1 + bb.x;
            v1.y = (float)acc[t][n][3] * sscl + corr1 + bb.y;
            *reinterpret_cast<float2*>(out + (size_t)r0 * N_TOTAL + col) = v0;
            *reinterpret_cast<float2*>(out + (size_t)(r0 + 8) * N_TOTAL + col) = v1;
        }
    }
}

// ---------------- launch ----------------
extern "C" void kernel_launch(void* const* d_in, const int* in_sizes, int n_in,
                              void* d_out, int out_size) {
    (void)in_sizes; (void)n_in; (void)out_size;
    const float* x     = (const float*)d_in[0];
    const int*   w     = (const int*)  d_in[1];
    const float* scale = (const float*)d_in[2];
    const float* zp    = (const float*)d_in[3];
    const float* bias  = (const float*)d_in[4];
    float* out = (float*)d_out;

    k_reset<<<1, 1>>>();
    k_max<<<1024, 256>>>((const float4*)x);
    k_scale<<<1, 1>>>(zp);
    k_rowsum<<<M_TOTAL, 256>>>(x);
    cvt_x_kernel<<<(M_TOTAL * (size_t)K_TOTAL / 4) / 256, 256>>>((const float4*)x);
    cvt_w_kernel<<<((size_t)N_TOTAL * K_TOTAL / 4) / 256, 256>>>((const int4*)w, zp);

    static int smem_set = 0;
    if (!smem_set) {
        cudaFuncSetAttribute(gemm_imma_kernel,
                             cudaFuncAttributeMaxDynamicSharedMemorySize, SMEM_TOTAL);
        smem_set = 1;
    }
    dim3 grid(M_TOTAL / BM, N_TOTAL / BN);
    gemm_imma_kernel<<<grid, 256, SMEM_TOTAL>>>(scale, bias, out);
}

// round 9
// speedup vs baseline: 5.6946x; 5.6946x over previous
#include <cuda_runtime.h>
#include <cuda_fp16.h>
#include <cstdint>
#include <cstddef>

#define M_TOTAL 4096
#define N_TOTAL 16384
#define K_TOTAL 4096
#define BM 128
#define BN 128
#define BK 64
#define KT (K_TOTAL / BK)               // 64
#define STAGES 3
#define A_STAGE_BYTES (BM * BK * 2)     // 16 KB
#define B_STAGE_BYTES (BN * BK * 2)     // 16 KB
#define STAGE_BYTES (A_STAGE_BYTES + B_STAGE_BYTES)   // 32 KB
#define SMEM_TOTAL (STAGES * STAGE_BYTES)             // 96 KB

// fp16 scratch (pre-dequantized). __device__ globals are the sanctioned scratch path.
__device__ __align__(1024) __half g_Xh[M_TOTAL * (size_t)K_TOTAL];   // 32 MB
__device__ __align__(1024) __half g_Wh[(size_t)N_TOTAL * K_TOTAL];   // 128 MB

// ---------------- helpers ----------------
__device__ __forceinline__ uint32_t smem_u32(const void* p) {
    uint32_t a;
    asm("{ .reg .u64 t; cvta.to.shared.u64 t, %1; cvt.u32.u64 %0, t; }" : "=r"(a) : "l"(p));
    return a;
}

__device__ __forceinline__ void ldsm_x4(uint32_t& r0, uint32_t& r1, uint32_t& r2, uint32_t& r3,
                                        uint32_t addr) {
    asm volatile("ldmatrix.sync.aligned.m8n8.x4.shared.b16 {%0,%1,%2,%3}, [%4];"
                 : "=r"(r0), "=r"(r1), "=r"(r2), "=r"(r3) : "r"(addr));
}

__device__ __forceinline__ void mma16816(float* c,
                                         uint32_t a0, uint32_t a1, uint32_t a2, uint32_t a3,
                                         uint32_t b0, uint32_t b1) {
    asm volatile(
        "mma.sync.aligned.m16n8k16.row.col.f32.f16.f16.f32 "
        "{%0,%1,%2,%3}, {%4,%5,%6,%7}, {%8,%9}, {%0,%1,%2,%3};"
        : "+f"(c[0]), "+f"(c[1]), "+f"(c[2]), "+f"(c[3])
        : "r"(a0), "r"(a1), "r"(a2), "r"(a3), "r"(b0), "r"(b1));
}

// ---------------- conversion kernels ----------------
__global__ void __launch_bounds__(256) cvt_x_kernel(const float4* __restrict__ x) {
    int i = blockIdx.x * blockDim.x + threadIdx.x;   // exact grid
    float4 v = x[i];
    __half2 h0 = __floats2half2_rn(v.x, v.y);
    __half2 h1 = __floats2half2_rn(v.z, v.w);
    uint2 o;
    o.x = *reinterpret_cast<uint32_t*>(&h0);
    o.y = *reinterpret_cast<uint32_t*>(&h1);
    *reinterpret_cast<uint2*>(&g_Xh[(size_t)i * 4]) = o;
}

__global__ void __launch_bounds__(256) cvt_w_kernel(const int4* __restrict__ w,
                                                    const float* __restrict__ zp) {
    float z = __ldg(zp);
    int i = blockIdx.x * blockDim.x + threadIdx.x;
    int4 q = w[i];
    __half2 h0 = __floats2half2_rn((float)q.x - z, (float)q.y - z);   // exact in fp16
    __half2 h1 = __floats2half2_rn((float)q.z - z, (float)q.w - z);
    uint2 o;
    o.x = *reinterpret_cast<uint32_t*>(&h0);
    o.y = *reinterpret_cast<uint32_t*>(&h1);
    *reinterpret_cast<uint2*>(&g_Wh[(size_t)i * 4]) = o;
}

// ---------------- pipelined HMMA GEMM, 64x64 warp tiles ----------------
// C[4096,16384] = Xh[4096,4096] @ Wh[16384,4096]^T  (both K-major), *scale + bias
__global__ void __launch_bounds__(128, 2)
gemm_hmma_kernel(const float* __restrict__ scale_p,
                 const float* __restrict__ bias,
                 float* __restrict__ out)
{
    extern __shared__ __align__(1024) char smem[];
    const uint32_t smem_base = smem_u32(smem);
    const int tid  = threadIdx.x;
    const int wid  = tid >> 5;
    const int lane = tid & 31;
    const int mw = wid & 1;          // 2 warps along M (64 rows each)
    const int nw = wid >> 1;         // 2 warps along N (64 cols each)
    const int mtile = blockIdx.x;
    const int ntile = blockIdx.y;

    const __half* gA = g_Xh + (size_t)mtile * BM * K_TOTAL;
    const __half* gB = g_Wh + (size_t)ntile * BN * K_TOTAL;

    // producer: per stage A = 1024 16B chunks + B = 1024; 128 threads, 8+8 each
    auto load_stage = [&](int kt, int stage) {
        const uint32_t sA = smem_base + stage * STAGE_BYTES;
        const uint32_t sB = sA + A_STAGE_BYTES;
        const char* pA = (const char*)gA + (size_t)kt * (BK * 2);
        const char* pB = (const char*)gB + (size_t)kt * (BK * 2);
#pragma unroll
        for (int i = 0; i < 8; i++) {
            int ci  = i * 128 + tid;
            int row = ci >> 3;                 // 0..127
            int c   = ci & 7;                  // 16B chunk within 128B row
            uint32_t off = (uint32_t)(row * 128 + c * 16);
            uint32_t sw  = off ^ ((off >> 3) & 0x70);
            asm volatile("cp.async.cg.shared.global [%0], [%1], 16;"
                         :: "r"(sA + sw), "l"(pA + (size_t)row * (K_TOTAL * 2) + c * 16));
            asm volatile("cp.async.cg.shared.global [%0], [%1], 16;"
                         :: "r"(sB + sw), "l"(pB + (size_t)row * (K_TOTAL * 2) + c * 16));
        }
        asm volatile("cp.async.commit_group;" ::: "memory");
    };

    // ldmatrix lane address prep (tile-relative): addr = base + ((lin + ks*32) ^ xor)
    uint32_t aLin[4], aXor[4];
#pragma unroll
    for (int t = 0; t < 4; t++) {
        int row = mw * 64 + t * 16 + (lane & 15);
        aLin[t] = (uint32_t)(row * 128 + (lane >> 4) * 16);
        aXor[t] = (uint32_t)((row * 16) & 0x70);
    }
    uint32_t bLin[4], bXor[4];
#pragma unroll
    for (int u = 0; u < 4; u++) {
        int g = lane >> 3, r = lane & 7;
        int row = nw * 64 + u * 16 + ((g >> 1) << 3) + r;
        bLin[u] = (uint32_t)(row * 128 + (g & 1) * 16);
        bXor[u] = (uint32_t)((row * 16) & 0x70);
    }

    float acc[4][8][4];
#pragma unroll
    for (int t = 0; t < 4; t++)
#pragma unroll
        for (int n = 0; n < 8; n++)
#pragma unroll
            for (int j = 0; j < 4; j++) acc[t][n][j] = 0.0f;

    load_stage(0, 0);
    load_stage(1, 1);

    for (int kt = 0; kt < KT; kt++) {
        asm volatile("cp.async.wait_group %0;" :: "n"(STAGES - 2) : "memory");
        __syncthreads();

        const int pf = kt + STAGES - 1;
        if (pf < KT) {
            load_stage(pf, pf % STAGES);
        } else {
            asm volatile("cp.async.commit_group;" ::: "memory");
        }

        const uint32_t sA = smem_base + (kt % STAGES) * STAGE_BYTES;
        const uint32_t sB = sA + A_STAGE_BYTES;
#pragma unroll
        for (int ks = 0; ks < 4; ks++) {
            uint32_t a[4][4];
#pragma unroll
            for (int t = 0; t < 4; t++)
                ldsm_x4(a[t][0], a[t][1], a[t][2], a[t][3],
                        sA + ((aLin[t] + ks * 32) ^ aXor[t]));
            uint32_t b[4][4];
#pragma unroll
            for (int u = 0; u < 4; u++)
                ldsm_x4(b[u][0], b[u][1], b[u][2], b[u][3],
                        sB + ((bLin[u] + ks * 32) ^ bXor[u]));
#pragma unroll
            for (int t = 0; t < 4; t++)
#pragma unroll
                for (int n = 0; n < 8; n++) {
                    uint32_t b0 = b[n >> 1][(n & 1) * 2 + 0];
                    uint32_t b1 = b[n >> 1][(n & 1) * 2 + 1];
                    mma16816(acc[t][n], a[t][0], a[t][1], a[t][2], a[t][3], b0, b1);
                }
        }
    }

    // epilogue: out = acc*scale + bias
    const float scl = __ldg(scale_p);
    const int rbase = mtile * BM + mw * 64 + (lane >> 2);
    const int cbase = ntile * BN + nw * 64 + (lane & 3) * 2;
#pragma unroll
    for (int t = 0; t < 4; t++) {
        const int r0 = rbase + t * 16;
#pragma unroll
        for (int n = 0; n < 8; n++) {
            const int col = cbase + n * 8;
            const float2 bb = *reinterpret_cast<const float2*>(bias + col);
            float2 v0, v1;
            v0.x = acc[t][n][0] * scl + bb.x;
            v0.y = acc[t][n][1] * scl + bb.y;
            v1.x = acc[t][n][2] * scl + bb.x;
            v1.y = acc[t][n][3] * scl + bb.y;
            *reinterpret_cast<float2*>(out + (size_t)r0 * N_TOTAL + col) = v0;
            *reinterpret_cast<float2*>(out + (size_t)(r0 + 8) * N_TOTAL + col) = v1;
        }
    }
}

// ---------------- launch ----------------
extern "C" void kernel_launch(void* const* d_in, const int* in_sizes, int n_in,
                              void* d_out, int out_size) {
    (void)in_sizes; (void)n_in; (void)out_size;
    const float* x     = (const float*)d_in[0];
    const int*   w     = (const int*)  d_in[1];
    const float* scale = (const float*)d_in[2];
    const float* zp    = (const float*)d_in[3];
    const float* bias  = (const float*)d_in[4];
    float* out = (float*)d_out;

    cvt_x_kernel<<<(M_TOTAL * (size_t)K_TOTAL / 4) / 256, 256>>>((const float4*)x);
    cvt_w_kernel<<<((size_t)N_TOTAL * K_TOTAL / 4) / 256, 256>>>((const int4*)w, zp);

    static int smem_set = 0;
    if (!smem_set) {
        cudaFuncSetAttribute(gemm_hmma_kernel,
                             cudaFuncAttributeMaxDynamicSharedMemorySize, SMEM_TOTAL);
        smem_set = 1;
    }
    dim3 grid(M_TOTAL / BM, N_TOTAL / BN);
    gemm_hmma_kernel<<<grid, 128, SMEM_TOTAL>>>(scale, bias, out);
}

// round 10
// speedup vs baseline: 6.0146x; 1.0562x over previous
#include <cuda_runtime.h>
#include <cuda_fp16.h>
#include <cstdint>
#include <cstddef>

#define M_TOTAL 4096
#define N_TOTAL 16384
#define K_TOTAL 4096
#define BM 128
#define BN 128
#define BK 64
#define KT (K_TOTAL / BK)               // 64
#define STAGES 3
#define A_STAGE_BYTES (BM * BK * 2)     // 16 KB
#define B_STAGE_BYTES (BN * BK * 2)     // 16 KB
#define STAGE_BYTES (A_STAGE_BYTES + B_STAGE_BYTES)   // 32 KB
#define SMEM_TOTAL (STAGES * STAGE_BYTES)             // 96 KB

#define X_CHUNKS (M_TOTAL * (size_t)K_TOTAL / 4)      // 4,194,304 float4
#define W_CHUNKS ((size_t)N_TOTAL * K_TOTAL / 4)      // 16,777,216 int4

// fp16 scratch (pre-dequantized). __device__ globals are the sanctioned scratch path.
__device__ __align__(1024) __half g_Xh[M_TOTAL * (size_t)K_TOTAL];   // 32 MB
__device__ __align__(1024) __half g_Wh[(size_t)N_TOTAL * K_TOTAL];   // 128 MB

// ---------------- helpers ----------------
__device__ __forceinline__ uint32_t smem_u32(const void* p) {
    uint32_t a;
    asm("{ .reg .u64 t; cvta.to.shared.u64 t, %1; cvt.u32.u64 %0, t; }" : "=r"(a) : "l"(p));
    return a;
}

__device__ __forceinline__ void ldsm_x4(uint32_t& r0, uint32_t& r1, uint32_t& r2, uint32_t& r3,
                                        uint32_t addr) {
    asm volatile("ldmatrix.sync.aligned.m8n8.x4.shared.b16 {%0,%1,%2,%3}, [%4];"
                 : "=r"(r0), "=r"(r1), "=r"(r2), "=r"(r3) : "r"(addr));
}

__device__ __forceinline__ void mma16816(float* c,
                                         uint32_t a0, uint32_t a1, uint32_t a2, uint32_t a3,
                                         uint32_t b0, uint32_t b1) {
    asm volatile(
        "mma.sync.aligned.m16n8k16.row.col.f32.f16.f16.f32 "
        "{%0,%1,%2,%3}, {%4,%5,%6,%7}, {%8,%9}, {%0,%1,%2,%3};"
        : "+f"(c[0]), "+f"(c[1]), "+f"(c[2]), "+f"(c[3])
        : "r"(a0), "r"(a1), "r"(a2), "r"(a3), "r"(b0), "r"(b1));
}

// ---------------- fused conversion kernel ----------------
// One launch converts both X (f32 -> f16, exact-ish) and W (int -> f16(q-zp), exact).
// Thread i handles W chunk i; threads with i < X_CHUNKS also handle X chunk i,
// overlapping the two memory streams.
__global__ void __launch_bounds__(256) cvt_all_kernel(const float4* __restrict__ x,
                                                      const int4* __restrict__ w,
                                                      const float* __restrict__ zp) {
    const size_t i = (size_t)blockIdx.x * blockDim.x + threadIdx.x;   // exact grid for W
    {
        const float z = __ldg(zp);
        int4 q = w[i];
        __half2 h0 = __floats2half2_rn((float)q.x - z, (float)q.y - z);
        __half2 h1 = __floats2half2_rn((float)q.z - z, (float)q.w - z);
        uint2 o;
        o.x = *reinterpret_cast<uint32_t*>(&h0);
        o.y = *reinterpret_cast<uint32_t*>(&h1);
        *reinterpret_cast<uint2*>(&g_Wh[i * 4]) = o;
    }
    if (i < X_CHUNKS) {
        float4 v = x[i];
        __half2 h0 = __floats2half2_rn(v.x, v.y);
        __half2 h1 = __floats2half2_rn(v.z, v.w);
        uint2 o;
        o.x = *reinterpret_cast<uint32_t*>(&h0);
        o.y = *reinterpret_cast<uint32_t*>(&h1);
        *reinterpret_cast<uint2*>(&g_Xh[i * 4]) = o;
    }
}

// ---------------- pipelined HMMA GEMM (R2 config, proven best) ----------------
// C[4096,16384] = Xh[4096,4096] @ Wh[16384,4096]^T  (both K-major), *scale + bias
__global__ void __launch_bounds__(256, 2)
gemm_hmma_kernel(const float* __restrict__ scale_p,
                 const float* __restrict__ bias,
                 float* __restrict__ out)
{
    extern __shared__ __align__(1024) char smem[];
    const uint32_t smem_base = smem_u32(smem);
    const int tid  = threadIdx.x;
    const int wid  = tid >> 5;
    const int lane = tid & 31;
    const int mw = wid & 3;          // 4 warps along M (32 rows each)
    const int nw = wid >> 2;         // 2 warps along N (64 cols each)

    // CTA rasterization swizzle: 16 groups of 16x16 tiles -> squarer wave footprint
    const int bid = blockIdx.x + (blockIdx.y << 5);   // 0..4095
    const int lid = bid & 255;
    const int gid = bid >> 8;                          // 0..15
    const int mtile = ((gid & 1) << 4) + (lid & 15);   // 0..31
    const int ntile = ((gid >> 1) << 4) + (lid >> 4);  // 0..127

    const __half* gA = g_Xh + (size_t)mtile * BM * K_TOTAL;
    const __half* gB = g_Wh + (size_t)ntile * BN * K_TOTAL;

    auto load_stage = [&](int kt, int stage) {
        const uint32_t sA = smem_base + stage * STAGE_BYTES;
        const uint32_t sB = sA + A_STAGE_BYTES;
        const char* pA = (const char*)gA + (size_t)kt * (BK * 2);
        const char* pB = (const char*)gB + (size_t)kt * (BK * 2);
#pragma unroll
        for (int i = 0; i < 4; i++) {
            int ci  = i * 256 + tid;
            int row = ci >> 3;                 // 0..127
            int c   = ci & 7;                  // 16B chunk within 128B row
            uint32_t off = (uint32_t)(row * 128 + c * 16);
            uint32_t sw  = off ^ ((off >> 3) & 0x70);
            asm volatile("cp.async.cg.shared.global [%0], [%1], 16;"
                         :: "r"(sA + sw), "l"(pA + (size_t)row * (K_TOTAL * 2) + c * 16));
            asm volatile("cp.async.cg.shared.global [%0], [%1], 16;"
                         :: "r"(sB + sw), "l"(pB + (size_t)row * (K_TOTAL * 2) + c * 16));
        }
        asm volatile("cp.async.commit_group;" ::: "memory");
    };

    // ldmatrix lane address prep (tile-relative): addr = base + ((lin + ks*32) ^ xor)
    uint32_t aLin[2], aXor[2];
#pragma unroll
    for (int t = 0; t < 2; t++) {
        int row = mw * 32 + t * 16 + (lane & 15);
        aLin[t] = (uint32_t)(row * 128 + (lane >> 4) * 16);
        aXor[t] = (uint32_t)((row * 16) & 0x70);
    }
    uint32_t bLin[4], bXor[4];
#pragma unroll
    for (int u = 0; u < 4; u++) {
        int g = lane >> 3, r = lane & 7;
        int row = nw * 64 + u * 16 + ((g >> 1) << 3) + r;
        bLin[u] = (uint32_t)(row * 128 + (g & 1) * 16);
        bXor[u] = (uint32_t)((row * 16) & 0x70);
    }

    float acc[2][8][4];
#pragma unroll
    for (int t = 0; t < 2; t++)
#pragma unroll
        for (int n = 0; n < 8; n++)
#pragma unroll
            for (int j = 0; j < 4; j++) acc[t][n][j] = 0.0f;

    load_stage(0, 0);
    load_stage(1, 1);

    for (int kt = 0; kt < KT; kt++) {
        asm volatile("cp.async.wait_group %0;" :: "n"(STAGES - 2) : "memory");
        __syncthreads();

        const int pf = kt + STAGES - 1;
        if (pf < KT) {
            load_stage(pf, pf % STAGES);
        } else {
            asm volatile("cp.async.commit_group;" ::: "memory");
        }

        const uint32_t sA = smem_base + (kt % STAGES) * STAGE_BYTES;
        const uint32_t sB = sA + A_STAGE_BYTES;
#pragma unroll
        for (int ks = 0; ks < 4; ks++) {
            uint32_t a[2][4];
#pragma unroll
            for (int t = 0; t < 2; t++)
                ldsm_x4(a[t][0], a[t][1], a[t][2], a[t][3],
                        sA + ((aLin[t] + ks * 32) ^ aXor[t]));
            uint32_t b[4][4];
#pragma unroll
            for (int u = 0; u < 4; u++)
                ldsm_x4(b[u][0], b[u][1], b[u][2], b[u][3],
                        sB + ((bLin[u] + ks * 32) ^ bXor[u]));
#pragma unroll
            for (int t = 0; t < 2; t++)
#pragma unroll
                for (int n = 0; n < 8; n++) {
                    uint32_t b0 = b[n >> 1][(n & 1) * 2 + 0];
                    uint32_t b1 = b[n >> 1][(n & 1) * 2 + 1];
                    mma16816(acc[t][n], a[t][0], a[t][1], a[t][2], a[t][3], b0, b1);
                }
        }
    }

    // epilogue: out = acc*scale + bias
    const float scl = __ldg(scale_p);
    const int rbase = mtile * BM + mw * 32 + (lane >> 2);
    const int cbase = ntile * BN + nw * 64 + (lane & 3) * 2;
#pragma unroll
    for (int t = 0; t < 2; t++) {
        const int r0 = rbase + t * 16;
#pragma unroll
        for (int n = 0; n < 8; n++) {
            const int col = cbase + n * 8;
            const float2 bb = *reinterpret_cast<const float2*>(bias + col);
            float2 v0, v1;
            v0.x = acc[t][n][0] * scl + bb.x;
            v0.y = acc[t][n][1] * scl + bb.y;
            v1.x = acc[t][n][2] * scl + bb.x;
            v1.y = acc[t][n][3] * scl + bb.y;
            *reinterpret_cast<float2*>(out + (size_t)r0 * N_TOTAL + col) = v0;
            *reinterpret_cast<float2*>(out + (size_t)(r0 + 8) * N_TOTAL + col) = v1;
        }
    }
}

// ---------------- launch ----------------
extern "C" void kernel_launch(void* const* d_in, const int* in_sizes, int n_in,
                              void* d_out, int out_size) {
    (void)in_sizes; (void)n_in; (void)out_size;
    const float* x     = (const float*)d_in[0];
    const int*   w     = (const int*)  d_in[1];
    const float* scale = (const float*)d_in[2];
    const float* zp    = (const float*)d_in[3];
    const float* bias  = (const float*)d_in[4];
    float* out = (float*)d_out;

    cvt_all_kernel<<<(unsigned)(W_CHUNKS / 256), 256>>>((const float4*)x, (const int4*)w, zp);

    static int smem_set = 0;
    if (!smem_set) {
        cudaFuncSetAttribute(gemm_hmma_kernel,
                             cudaFuncAttributeMaxDynamicSharedMemorySize, SMEM_TOTAL);
        smem_set = 1;
    }
    dim3 grid(M_TOTAL / BM, N_TOTAL / BN);
    gemm_hmma_kernel<<<grid, 256, SMEM_TOTAL>>>(scale, bias, out);
}